// round 16
// baseline (speedup 1.0000x reference)
#include <cuda_runtime.h>
#include <cuda_bf16.h>
#include <math.h>
#include <stdint.h>

#define NMAX 4096
#define NTOT 8192            // both graphs stacked
#define DH   256
#define DCAT 896
#define EMAX 65536
#define WTOT 720896

// ---------------- scratch (device globals; no runtime alloc) ----------------
__device__ __align__(16) __nv_bfloat16 g_Xh[(size_t)NTOT * DCAT];
__device__ __align__(16) __nv_bfloat16 g_Xl[(size_t)NTOT * DCAT];
__device__ __align__(16) __nv_bfloat16 g_Wth[WTOT];
__device__ __align__(16) __nv_bfloat16 g_Wtl[WTOT];
__device__ __align__(16) float g_tmp12[(size_t)NTOT * 512];
__device__ __align__(16) float g_agg1[(size_t)NTOT * DH];
__device__ __align__(16) float g_agg2[(size_t)NTOT * DH];
__device__ __align__(16) float g_H[(size_t)NTOT * DH];
__device__ __align__(16) float g_E[(size_t)NMAX * NMAX];   // 64MB (L2-resident)
__device__ __align__(16) float g_r[NMAX];
__device__ __align__(16) float g_csum[5 * NMAX];
__device__ __align__(16) float g_cinv[NMAX];
__device__ __align__(16) int   g_cnt_a[NTOT];
__device__ __align__(16) int   g_cnt_b[NTOT];
__device__ __align__(16) float g_inv_a[NTOT];
__device__ __align__(16) float g_inv_b[NTOT];
__device__ __align__(16) int g_off_a[NTOT];
__device__ __align__(16) int g_off_b[NTOT];
__device__ __align__(16) int g_cur_a[NTOT];
__device__ __align__(16) int g_cur_b[NTOT];
__device__ __align__(16) int g_lst_a[2 * EMAX];
__device__ __align__(16) int g_lst_b[2 * EMAX];
__device__ __align__(16) __nv_bfloat16 g_sh[(size_t)NTOT * DH];
__device__ __align__(16) __nv_bfloat16 g_sl[(size_t)NTOT * DH];

// ---------------- PTX helpers ----------------
__device__ __forceinline__ uint32_t smem_u32(const void* p) {
    uint32_t a;
    asm("{ .reg .u64 t; cvta.to.shared.u64 t, %1; cvt.u32.u64 %0, t; }" : "=r"(a) : "l"(p));
    return a;
}
#define CP_ASYNC16(saddr, gptr) \
    asm volatile("cp.async.cg.shared.global [%0], [%1], 16;" :: "r"(saddr), "l"(gptr))
#define CP_COMMIT() asm volatile("cp.async.commit_group;" ::: "memory")
#define CP_WAIT1()  asm volatile("cp.async.wait_group 1;" ::: "memory")

__device__ __forceinline__ void ldm_x4(uint32_t* r, uint32_t addr) {
    asm volatile("ldmatrix.sync.aligned.m8n8.x4.shared.b16 {%0,%1,%2,%3}, [%4];"
        : "=r"(r[0]), "=r"(r[1]), "=r"(r[2]), "=r"(r[3]) : "r"(addr));
}
__device__ __forceinline__ void mma_bf16(float* d, const uint32_t* a, uint32_t b0, uint32_t b1) {
    asm volatile(
        "mma.sync.aligned.m16n8k16.row.col.f32.bf16.bf16.f32 "
        "{%0,%1,%2,%3}, {%4,%5,%6,%7}, {%8,%9}, {%0,%1,%2,%3};"
        : "+f"(d[0]), "+f"(d[1]), "+f"(d[2]), "+f"(d[3])
        : "r"(a[0]), "r"(a[1]), "r"(a[2]), "r"(a[3]), "r"(b0), "r"(b1));
}

// ---------------- utility kernels ----------------
__global__ void fillinit_k(int* __restrict__ ca, int* __restrict__ cb,
                           float* __restrict__ cs)
{
    int t = blockIdx.x * blockDim.x + threadIdx.x;
    if (t < NTOT) { ca[t] = 0; cb[t] = 0; }
    if (t < 5 * NMAX) cs[t] = 0.f;
}
__global__ void recip_k(const float* __restrict__ a, float* __restrict__ b, int n) {
    int t = blockIdx.x * blockDim.x + threadIdx.x;
    if (t < n) b[t] = 1.0f / a[t];
}
__global__ void count_both(const int* __restrict__ d0, const int* __restrict__ s0, int E0,
                           const int* __restrict__ d1, const int* __restrict__ s1, int E1,
                           int* __restrict__ ca, int* __restrict__ cb)
{
    int t = blockIdx.x * blockDim.x + threadIdx.x;
    if (t < E0) {
        atomicAdd(&ca[d0[t]], 1); atomicAdd(&cb[s0[t]], 1);
    } else if (t < E0 + E1) {
        int u = t - E0;
        atomicAdd(&ca[NMAX + d1[u]], 1); atomicAdd(&cb[NMAX + s1[u]], 1);
    }
}
__global__ void scan4_k(const int* __restrict__ ca, const int* __restrict__ cb,
                        int* __restrict__ oa, int* __restrict__ ob,
                        int* __restrict__ ra, int* __restrict__ rb,
                        float* __restrict__ ia, float* __restrict__ ib, int E0)
{
    __shared__ int s[NMAX];
    int b = blockIdx.x;
    int gi = b & 1, dir = b >> 1;
    const int* cnt = (dir ? cb : ca) + gi * NMAX;
    int* off = (dir ? ob : oa) + gi * NMAX;
    int* cur = (dir ? rb : ra) + gi * NMAX;
    float* inv = (dir ? ib : ia) + gi * NMAX;
    int base = gi ? E0 : 0;
    int tid = threadIdx.x;
    #pragma unroll
    for (int j = 0; j < 4; j++) s[tid + j * 1024] = cnt[tid + j * 1024];
    __syncthreads();
    for (int d = 1; d < NMAX; d <<= 1) {
        int v[4];
        #pragma unroll
        for (int j = 0; j < 4; j++) {
            int i = tid + j * 1024;
            v[j] = (i >= d) ? s[i - d] : 0;
        }
        __syncthreads();
        #pragma unroll
        for (int j = 0; j < 4; j++) s[tid + j * 1024] += v[j];
        __syncthreads();
    }
    #pragma unroll
    for (int j = 0; j < 4; j++) {
        int i = tid + j * 1024;
        int c = cnt[i];
        int o = base + s[i] - c;
        off[i] = o;
        cur[i] = o;
        inv[i] = 1.0f / (float)max(c, 1);
    }
}
__global__ void place_both(const int* __restrict__ d0, const int* __restrict__ s0, int E0,
                           const int* __restrict__ d1, const int* __restrict__ s1, int E1,
                           int* __restrict__ ca, int* __restrict__ cb,
                           int* __restrict__ la, int* __restrict__ lb)
{
    int t = blockIdx.x * blockDim.x + threadIdx.x;
    if (t < E0) {
        int d = d0[t], s = s0[t];
        la[atomicAdd(&ca[d], 1)] = s;
        lb[atomicAdd(&cb[s], 1)] = d;
    } else if (t < E0 + E1) {
        int u = t - E0;
        int d = d1[u], s = s1[u];
        la[atomicAdd(&ca[NMAX + d], 1)] = NMAX + s;
        lb[atomicAdd(&cb[NMAX + s], 1)] = NMAX + d;
    }
}

// merged CSR gather-mean for BOTH directions: grid = 2*NTOT, 64 thr
__global__ void __launch_bounds__(64) gather2_k(
    const float* __restrict__ tmp12,
    const int* __restrict__ off_a, const int* __restrict__ cnt_a,
    const float* __restrict__ inv_a, const int* __restrict__ lst_a,
    float* __restrict__ agg1,
    const int* __restrict__ off_b, const int* __restrict__ cnt_b,
    const float* __restrict__ inv_b, const int* __restrict__ lst_b,
    float* __restrict__ agg2)
{
    __shared__ int sl[64];
    int n = blockIdx.x;
    const bool dirB = n >= NTOT;
    if (dirB) n -= NTOT;
    const float* vals = dirB ? tmp12 + 256 : tmp12;
    const int* off = dirB ? off_b : off_a;
    const int* cnt = dirB ? cnt_b : cnt_a;
    const float* inv = dirB ? inv_b : inv_a;
    const int* lst = dirB ? lst_b : lst_a;
    float* out = dirB ? agg2 : agg1;

    const int tid = threadIdx.x;
    const int beg = off[n];
    const int d = cnt[n];
    const int c4 = tid * 4;
    float4 acc = make_float4(0.f, 0.f, 0.f, 0.f);
    for (int base = 0; base < d; base += 64) {
        int chunk = min(64, d - base);
        if (tid < chunk) sl[tid] = lst[beg + base + tid];
        __syncthreads();
        int e = 0;
        for (; e + 4 <= chunk; e += 4) {
            float4 v0 = *reinterpret_cast<const float4*>(vals + (size_t)sl[e] * 512 + c4);
            float4 v1 = *reinterpret_cast<const float4*>(vals + (size_t)sl[e + 1] * 512 + c4);
            float4 v2 = *reinterpret_cast<const float4*>(vals + (size_t)sl[e + 2] * 512 + c4);
            float4 v3 = *reinterpret_cast<const float4*>(vals + (size_t)sl[e + 3] * 512 + c4);
            acc.x += (v0.x + v1.x) + (v2.x + v3.x);
            acc.y += (v0.y + v1.y) + (v2.y + v3.y);
            acc.z += (v0.z + v1.z) + (v2.z + v3.z);
            acc.w += (v0.w + v1.w) + (v2.w + v3.w);
        }
        for (; e < chunk; e++) {
            float4 v = *reinterpret_cast<const float4*>(vals + (size_t)sl[e] * 512 + c4);
            acc.x += v.x; acc.y += v.y; acc.z += v.z; acc.w += v.w;
        }
        __syncthreads();
    }
    float iv = inv[n];
    acc.x *= iv; acc.y *= iv; acc.z *= iv; acc.w *= iv;
    *reinterpret_cast<float4*>(out + (size_t)n * DH + c4) = acc;
}

// both graphs' input features -> bf16 hi/lo into X cols 0..127
__global__ void copyx_both(const float* __restrict__ xs, int NS,
                           const float* __restrict__ xt, int NT,
                           __nv_bfloat16* __restrict__ Xh, __nv_bfloat16* __restrict__ Xl)
{
    int t = blockIdx.x * blockDim.x + threadIdx.x;
    int n0 = NS * 128;
    float v;
    size_t dsti;
    if (t < n0) {
        v = xs[t];
        dsti = (size_t)(t >> 7) * DCAT + (t & 127);
    } else if (t < n0 + NT * 128) {
        int u = t - n0;
        v = xt[u];
        dsti = (size_t)(NMAX + (u >> 7)) * DCAT + (u & 127);
    } else return;
    __nv_bfloat16 h = __float2bfloat16(v);
    Xh[dsti] = h;
    Xl[dsti] = __float2bfloat16(v - __bfloat162float(h));
}

// all weights transpose+split in one kernel
struct WPack {
    const float* src[10];
    int dstoff[10];
    int K[10];
    int start[11];
};
__global__ void wtsplit_all(WPack wp, __nv_bfloat16* __restrict__ th,
                            __nv_bfloat16* __restrict__ tl)
{
    int t = blockIdx.x * blockDim.x + threadIdx.x;
    if (t >= WTOT) return;
    int seg = 0;
    #pragma unroll
    for (int i = 1; i < 10; i++) seg += (t >= wp.start[i]);
    int u = t - wp.start[seg];
    int K = wp.K[seg];
    int k = u >> 8, n = u & 255;          // src layout [K][256]
    float v = wp.src[seg][u];
    __nv_bfloat16 h = __float2bfloat16(v);
    size_t di = (size_t)wp.dstoff[seg] + (size_t)n * K + k;
    th[di] = h;
    tl[di] = __float2bfloat16(v - __bfloat162float(h));
}

// ---------------- fused GNN GEMM (single k-loop, cp.async 2-stage) ----------
#define GSP 40

template <int EPI>
__global__ void __launch_bounds__(128) gemm_f(
    const __nv_bfloat16* __restrict__ Ah, const __nv_bfloat16* __restrict__ Al, int lda,
    const __nv_bfloat16* __restrict__ Bh, const __nv_bfloat16* __restrict__ Bl,
    float* __restrict__ C, int ldc, int M, int K,
    const float* __restrict__ bias, const float* __restrict__ add1,
    const float* __restrict__ add2,
    __nv_bfloat16* __restrict__ Oh, __nv_bfloat16* __restrict__ Ol)
{
    __shared__ __nv_bfloat16 s[2][4][64 * GSP];
    const int tid = threadIdx.x;
    const int lane = tid & 31, wid = tid >> 5;
    const int wm = wid & 1, wn = wid >> 1;
    const int row0 = blockIdx.y * 64, col0 = blockIdx.x * 64;
    const int nk = K / 32;

    const __nv_bfloat16* base[4] = {
        Ah + (size_t)row0 * lda, Al + (size_t)row0 * lda,
        Bh + (size_t)col0 * K, Bl + (size_t)col0 * K };
    const int ld4[4] = { lda, lda, K, K };

    const int l_row = tid >> 1;
    const int l_q0 = (tid & 1) * 2;

    auto load_stage = [&](int kc, int st) {
        #pragma unroll
        for (int t4 = 0; t4 < 4; t4++) {
            const __nv_bfloat16* g = base[t4] + (size_t)l_row * ld4[t4] + kc * 32;
            uint32_t sa = smem_u32(&s[st][t4][l_row * GSP]);
            CP_ASYNC16(sa + (l_q0 + 0) * 16, g + (l_q0 + 0) * 8);
            CP_ASYNC16(sa + (l_q0 + 1) * 16, g + (l_q0 + 1) * 8);
        }
    };

    float acc[2][4][4];
    #pragma unroll
    for (int i = 0; i < 2; i++)
        #pragma unroll
        for (int j = 0; j < 4; j++)
            #pragma unroll
            for (int q = 0; q < 4; q++) acc[i][j][q] = 0.f;

    const int a_row = wm * 32 + (lane < 16 ? lane : lane - 16);
    const int a_col = (lane < 16 ? 0 : 8);
    const int b_row = wn * 32 + (lane & 7);
    const int b_col = (lane >> 3) * 8;

    load_stage(0, 0);
    CP_COMMIT();

    for (int kc = 0; kc < nk; kc++) {
        if (kc + 1 < nk) load_stage(kc + 1, (kc + 1) & 1);
        CP_COMMIT();
        CP_WAIT1();
        __syncthreads();
        const int st = kc & 1;

        uint32_t bh[4][4], bl[4][4];
        #pragma unroll
        for (int j = 0; j < 4; j++) {
            ldm_x4(bh[j], smem_u32(&s[st][2][(b_row + j * 8) * GSP + b_col]));
            ldm_x4(bl[j], smem_u32(&s[st][3][(b_row + j * 8) * GSP + b_col]));
        }
        #pragma unroll
        for (int h = 0; h < 2; h++) {
            #pragma unroll
            for (int i = 0; i < 2; i++) {
                uint32_t ah[4], al[4];
                ldm_x4(ah, smem_u32(&s[st][0][(a_row + i * 16) * GSP + h * 16 + a_col]));
                ldm_x4(al, smem_u32(&s[st][1][(a_row + i * 16) * GSP + h * 16 + a_col]));
                #pragma unroll
                for (int j = 0; j < 4; j++) {
                    mma_bf16(acc[i][j], ah, bh[j][2 * h], bh[j][2 * h + 1]);
                    mma_bf16(acc[i][j], ah, bl[j][2 * h], bl[j][2 * h + 1]);
                    mma_bf16(acc[i][j], al, bh[j][2 * h], bh[j][2 * h + 1]);
                }
            }
        }
        __syncthreads();
    }

    const int er = lane >> 2, ec = (lane & 3) * 2;
    #pragma unroll
    for (int i = 0; i < 2; i++) {
        #pragma unroll
        for (int j = 0; j < 4; j++) {
            int gc = col0 + wn * 32 + j * 8 + ec;
            #pragma unroll
            for (int rr = 0; rr < 2; rr++) {
                int row = row0 + wm * 32 + i * 16 + er + rr * 8;
                if (row >= M) continue;
                float v0 = acc[i][j][2 * rr + 0];
                float v1 = acc[i][j][2 * rr + 1];
                if (EPI == 0) {
                    *reinterpret_cast<float2*>(C + (size_t)row * ldc + gc) =
                        make_float2(v0, v1);
                } else if (EPI == 1) {
                    v0 = fmaxf(v0 + bias[gc] + add1[(size_t)row * DH + gc]
                                  + add2[(size_t)row * DH + gc], 0.f);
                    v1 = fmaxf(v1 + bias[gc + 1] + add1[(size_t)row * DH + gc + 1]
                                  + add2[(size_t)row * DH + gc + 1], 0.f);
                    __nv_bfloat16 h0 = __float2bfloat16(v0);
                    __nv_bfloat16 h1 = __float2bfloat16(v1);
                    __nv_bfloat16 l0 = __float2bfloat16(v0 - __bfloat162float(h0));
                    __nv_bfloat16 l1 = __float2bfloat16(v1 - __bfloat162float(h1));
                    __nv_bfloat162 hv; hv.x = h0; hv.y = h1;
                    __nv_bfloat162 lv; lv.x = l0; lv.y = l1;
                    *reinterpret_cast<__nv_bfloat162*>(Oh + (size_t)row * ldc + gc) = hv;
                    *reinterpret_cast<__nv_bfloat162*>(Ol + (size_t)row * ldc + gc) = lv;
                } else {  // EPI == 3
                    *reinterpret_cast<float2*>(C + (size_t)row * ldc + gc) =
                        make_float2(v0 + bias[gc], v1 + bias[gc + 1]);
                }
            }
        }
    }
}

// ---------------- match GEMM (3-pass, cp.async 2-stage) ----------------
#define SPAD 40

__global__ void __launch_bounds__(256, 2) match_mma_kernel(
    const __nv_bfloat16* __restrict__ Ah, const __nv_bfloat16* __restrict__ Al,
    const __nv_bfloat16* __restrict__ Bh, const __nv_bfloat16* __restrict__ Bl,
    float* __restrict__ Eout)
{
    __shared__ __nv_bfloat16 s[2][2][128 * SPAD];
    const int tid = threadIdx.x;
    const int wid = tid >> 5, lane = tid & 31;
    const int wm = wid & 3, wn = wid >> 2;
    const int row0 = blockIdx.y * 128, col0 = blockIdx.x * 128;

    const __nv_bfloat16* Asrc[3] = {
        Ah + (size_t)row0 * DH, Ah + (size_t)row0 * DH, Al + (size_t)row0 * DH };
    const __nv_bfloat16* Bsrc[3] = {
        Bh + (size_t)col0 * DH, Bl + (size_t)col0 * DH, Bh + (size_t)col0 * DH };

    const int l_row = tid >> 1;
    const int l_q0 = (tid & 1) * 2;

    auto load_stage = [&](int it, int st) {
        int p = it >> 3, kc = it & 7;
        const __nv_bfloat16* ga = Asrc[p] + (size_t)l_row * DH + kc * 32;
        const __nv_bfloat16* gb = Bsrc[p] + (size_t)l_row * DH + kc * 32;
        uint32_t sa = smem_u32(&s[st][0][l_row * SPAD]);
        uint32_t sb = smem_u32(&s[st][1][l_row * SPAD]);
        CP_ASYNC16(sa + (l_q0 + 0) * 16, ga + (l_q0 + 0) * 8);
        CP_ASYNC16(sa + (l_q0 + 1) * 16, ga + (l_q0 + 1) * 8);
        CP_ASYNC16(sb + (l_q0 + 0) * 16, gb + (l_q0 + 0) * 8);
        CP_ASYNC16(sb + (l_q0 + 1) * 16, gb + (l_q0 + 1) * 8);
    };

    float acc[2][8][4];
    #pragma unroll
    for (int i = 0; i < 2; i++)
        #pragma unroll
        for (int j = 0; j < 8; j++)
            #pragma unroll
            for (int q = 0; q < 4; q++) acc[i][j][q] = 0.f;

    const int a_row = wm * 32 + (lane < 16 ? lane : lane - 16);
    const int a_col = (lane < 16 ? 0 : 8);
    const int b_row = wn * 64 + (lane & 7);
    const int b_col = (lane >> 3) * 8;

    load_stage(0, 0);
    CP_COMMIT();

    for (int it = 0; it < 24; it++) {
        if (it + 1 < 24) load_stage(it + 1, (it + 1) & 1);
        CP_COMMIT();
        CP_WAIT1();
        __syncthreads();
        const int st = it & 1;

        uint32_t bfr[8][4];
        #pragma unroll
        for (int j = 0; j < 8; j++)
            ldm_x4(bfr[j], smem_u32(&s[st][1][(b_row + j * 8) * SPAD + b_col]));

        #pragma unroll
        for (int h = 0; h < 2; h++) {
            #pragma unroll
            for (int i = 0; i < 2; i++) {
                uint32_t afr[4];
                ldm_x4(afr, smem_u32(&s[st][0][(a_row + i * 16) * SPAD + h * 16 + a_col]));
                #pragma unroll
                for (int j = 0; j < 8; j++)
                    mma_bf16(acc[i][j], afr, bfr[j][2 * h], bfr[j][2 * h + 1]);
            }
        }
        __syncthreads();
    }

    const int er = lane >> 2, ec = (lane & 3) * 2;
    #pragma unroll
    for (int i = 0; i < 2; i++) {
        int gr0 = row0 + wm * 32 + i * 16 + er;
        #pragma unroll
        for (int j = 0; j < 8; j++) {
            int gc = col0 + wn * 64 + j * 8 + ec;
            float2 o0, o1;
            o0.x = __expf(20.f * (acc[i][j][0] + 1e-10f));
            o0.y = __expf(20.f * (acc[i][j][1] + 1e-10f));
            o1.x = __expf(20.f * (acc[i][j][2] + 1e-10f));
            o1.y = __expf(20.f * (acc[i][j][3] + 1e-10f));
            *reinterpret_cast<float2*>(Eout + (size_t)gr0 * NMAX + gc) = o0;
            *reinterpret_cast<float2*>(Eout + (size_t)(gr0 + 8) * NMAX + gc) = o1;
        }
    }
}

// ---------------- fused L2 normalize + bf16 split (zero dummy rows) --------
__global__ void l2split_k(const float* __restrict__ H, __nv_bfloat16* __restrict__ sh,
                          __nv_bfloat16* __restrict__ sl, int NS)
{
    int row = blockIdx.x;
    int tid = threadIdx.x;
    if (row >= NS && row < NMAX) {
        sh[(size_t)row * DH + tid] = __float2bfloat16(0.f);
        sl[(size_t)row * DH + tid] = __float2bfloat16(0.f);
        return;
    }
    float v = H[(size_t)row * DH + tid];
    __shared__ float red[256];
    red[tid] = v * v;
    __syncthreads();
    for (int s = 128; s > 0; s >>= 1) {
        if (tid < s) red[tid] += red[tid + s];
        __syncthreads();
    }
    float sc = 1.0f / fmaxf(sqrtf(red[0]), 1e-12f);
    float nv = v * sc;
    __nv_bfloat16 h = __float2bfloat16(nv);
    sh[(size_t)row * DH + tid] = h;
    sl[(size_t)row * DH + tid] = __float2bfloat16(nv - __bfloat162float(h));
}

// ---------------- sinkhorn factor passes ----------------
// colsum0, float4 per thread: grid (4, 128) = 512 CTAs, 32 rows per CTA
__global__ void colsum0_k(const float* __restrict__ Eb, float* __restrict__ cs)
{
    int j4 = blockIdx.x * 256 + threadIdx.x;     // 0..1023
    int i0 = blockIdx.y * 32;
    const float4* E4 = reinterpret_cast<const float4*>(Eb);
    float4 acc = make_float4(0.f, 0.f, 0.f, 0.f);
    #pragma unroll 4
    for (int i = 0; i < 32; i++) {
        float4 e = E4[(size_t)(i0 + i) * (NMAX / 4) + j4];
        acc.x += e.x; acc.y += e.y; acc.z += e.z; acc.w += e.w;
    }
    int c = j4 * 4;
    atomicAdd(&cs[c + 0], acc.x);
    atomicAdd(&cs[c + 1], acc.y);
    atomicAdd(&cs[c + 2], acc.z);
    atomicAdd(&cs[c + 3], acc.w);
}

// fused: rowsum(cs_prev) + colsum -> cs_next; grid 256 x 256 thr, 16 rows/block
__global__ void __launch_bounds__(256) fused_rc(const float* __restrict__ Eb,
                                                const float* __restrict__ cs_prev,
                                                float* __restrict__ cs_next)
{
    __shared__ float sc[NMAX];
    __shared__ float rinv_s[16];
    const int b = blockIdx.x, tid = threadIdx.x;
    const int lane = tid & 31, w = tid >> 5;
    for (int j = tid; j < NMAX; j += 256) sc[j] = 1.0f / cs_prev[j];
    __syncthreads();
    const float4* sc4 = reinterpret_cast<const float4*>(sc);
    // phase A: row sums (warp per row, 2 rows per warp)
    #pragma unroll
    for (int t = 0; t < 2; t++) {
        int row = b * 16 + t * 8 + w;
        const float4* rp = reinterpret_cast<const float4*>(Eb + (size_t)row * NMAX);
        float acc = 0.f;
        #pragma unroll 8
        for (int k = 0; k < 32; k++) {
            float4 e = rp[lane + k * 32];
            float4 s4 = sc4[lane + k * 32];
            acc += e.x * s4.x + e.y * s4.y + e.z * s4.z + e.w * s4.w;
        }
        #pragma unroll
        for (int o = 16; o; o >>= 1) acc += __shfl_xor_sync(0xffffffffu, acc, o);
        if (lane == 0) rinv_s[t * 8 + w] = 1.0f / acc;
    }
    __syncthreads();
    // phase B: column partials (warp owns 512-col slice, register accum over 16 rows)
    float4 cp[4];
    #pragma unroll
    for (int q = 0; q < 4; q++) cp[q] = make_float4(0.f, 0.f, 0.f, 0.f);
    const int fbase = w * 128 + lane;
    for (int r = 0; r < 16; r++) {
        float ri = rinv_s[r];
        const float4* rp = reinterpret_cast<const float4*>(Eb + (size_t)(b * 16 + r) * NMAX);
        #pragma unroll
        for (int q = 0; q < 4; q++) {
            float4 e = rp[fbase + q * 32];
            cp[q].x += e.x * ri; cp[q].y += e.y * ri;
            cp[q].z += e.z * ri; cp[q].w += e.w * ri;
        }
    }
    #pragma unroll
    for (int q = 0; q < 4; q++) {
        int c = (fbase + q * 32) * 4;
        atomicAdd(&cs_next[c + 0], cp[q].x);
        atomicAdd(&cs_next[c + 1], cp[q].y);
        atomicAdd(&cs_next[c + 2], cp[q].z);
        atomicAdd(&cs_next[c + 3], cp[q].w);
    }
}

// r[row] = 1/sum_j E[row][j]*cinv[j]; warp-per-row, 8 rows/block, grid 512
__global__ void __launch_bounds__(256) rowsum_k(const float* __restrict__ Eb,
                                                const float* __restrict__ cinv,
                                                float* __restrict__ r)
{
    __shared__ float sc[NMAX];
    const int tid = threadIdx.x, lane = tid & 31, w = tid >> 5;
    #pragma unroll
    for (int j = 0; j < 4; j++)
        reinterpret_cast<float4*>(sc)[tid + j * 256] =
            reinterpret_cast<const float4*>(cinv)[tid + j * 256];
    __syncthreads();
    const float4* sc4 = reinterpret_cast<const float4*>(sc);
    const int row = blockIdx.x * 8 + w;
    const float4* rp = reinterpret_cast<const float4*>(Eb + (size_t)row * NMAX);
    float acc = 0.f;
    #pragma unroll 8
    for (int k = 0; k < 32; k++) {
        float4 e = rp[lane + k * 32];
        float4 s4 = sc4[lane + k * 32];
        acc += e.x * s4.x + e.y * s4.y + e.z * s4.z + e.w * s4.w;
    }
    #pragma unroll
    for (int o = 16; o; o >>= 1) acc += __shfl_xor_sync(0xffffffffu, acc, o);
    if (lane == 0) r[row] = 1.0f / acc;
}

// out[i][j] = E[i][j]*r[i]*cinv[j]
__global__ void finalize_k(const float* __restrict__ Eb, const float* __restrict__ r,
                           const float* __restrict__ cinv, float* __restrict__ out, int rows)
{
    int t = blockIdx.x * blockDim.x + threadIdx.x;
    if (t >= rows * (NMAX / 4)) return;
    int i = t >> 10, j = t & 1023;
    float ri = r[i];
    float4 e = reinterpret_cast<const float4*>(Eb)[(size_t)i * (NMAX / 4) + j];
    float4 cv = reinterpret_cast<const float4*>(cinv)[j];
    float4 o;
    o.x = e.x * ri * cv.x; o.y = e.y * ri * cv.y;
    o.z = e.z * ri * cv.z; o.w = e.w * ri * cv.w;
    reinterpret_cast<float4*>(out)[t] = o;
}

// ---------------- host driver ----------------
static inline int cdiv(int a, int b) { return (a + b - 1) / b; }

extern "C" void kernel_launch(void* const* d_in, const int* in_sizes, int n_in,
                              void* d_out, int out_size)
{
    const float* x_s = (const float*)d_in[0];
    const float* x_t = (const float*)d_in[1];
    const int* edges = (const int*)d_in[2];
    const int* edget = (const int*)d_in[3];
    const float* W1[3], *W2[3], *Wr[3], *br[3];
    for (int l = 0; l < 3; l++) {
        W1[l] = (const float*)d_in[4 + 4 * l];
        W2[l] = (const float*)d_in[5 + 4 * l];
        Wr[l] = (const float*)d_in[6 + 4 * l];
        br[l] = (const float*)d_in[7 + 4 * l];
    }
    const float* final_w = (const float*)d_in[16];
    const float* final_b = (const float*)d_in[17];

    const int NS = in_sizes[0] / 128;
    const int NT = in_sizes[1] / 128;
    const int ES = in_sizes[2] / 2;
    const int ET = in_sizes[3] / 2;

    float *tmp12, *agg1, *agg2, *Hf, *Eb, *rr, *csum, *cinv, *inv_a, *inv_b;
    int *cnt_a, *cnt_b, *off_a, *off_b, *cur_a, *cur_b, *lst_a, *lst_b;
    __nv_bfloat16 *Xh, *Xl, *Wth, *Wtl, *sh, *sl;
    cudaGetSymbolAddress((void**)&Xh, g_Xh);
    cudaGetSymbolAddress((void**)&Xl, g_Xl);
    cudaGetSymbolAddress((void**)&Wth, g_Wth);
    cudaGetSymbolAddress((void**)&Wtl, g_Wtl);
    cudaGetSymbolAddress((void**)&tmp12, g_tmp12);
    cudaGetSymbolAddress((void**)&agg1, g_agg1);
    cudaGetSymbolAddress((void**)&agg2, g_agg2);
    cudaGetSymbolAddress((void**)&Hf, g_H);
    cudaGetSymbolAddress((void**)&Eb, g_E);
    cudaGetSymbolAddress((void**)&rr, g_r);
    cudaGetSymbolAddress((void**)&csum, g_csum);
    cudaGetSymbolAddress((void**)&cinv, g_cinv);
    cudaGetSymbolAddress((void**)&cnt_a, g_cnt_a);
    cudaGetSymbolAddress((void**)&cnt_b, g_cnt_b);
    cudaGetSymbolAddress((void**)&inv_a, g_inv_a);
    cudaGetSymbolAddress((void**)&inv_b, g_inv_b);
    cudaGetSymbolAddress((void**)&off_a, g_off_a);
    cudaGetSymbolAddress((void**)&off_b, g_off_b);
    cudaGetSymbolAddress((void**)&cur_a, g_cur_a);
    cudaGetSymbolAddress((void**)&cur_b, g_cur_b);
    cudaGetSymbolAddress((void**)&lst_a, g_lst_a);
    cudaGetSymbolAddress((void**)&lst_b, g_lst_b);
    cudaGetSymbolAddress((void**)&sh, g_sh);
    cudaGetSymbolAddress((void**)&sl, g_sl);

    // weight layout: per layer [W1;W2] fused [512][K], Wr [256][K], final [256][896]
    int woff12[3], woffr[3], wofff;
    {
        int o = 0, fan = 128;
        for (int l = 0; l < 3; l++) {
            woff12[l] = o; o += 512 * fan;
            woffr[l] = o;  o += 256 * fan;
            fan = DH;
        }
        wofff = o;
    }
    {
        WPack wp;
        int s = 0, fan = 128;
        int idx = 0;
        for (int l = 0; l < 3; l++) {
            wp.src[idx] = W1[l]; wp.dstoff[idx] = woff12[l];              wp.K[idx] = fan; wp.start[idx] = s; s += fan * 256; idx++;
            wp.src[idx] = W2[l]; wp.dstoff[idx] = woff12[l] + 256 * fan;  wp.K[idx] = fan; wp.start[idx] = s; s += fan * 256; idx++;
            wp.src[idx] = Wr[l]; wp.dstoff[idx] = woffr[l];               wp.K[idx] = fan; wp.start[idx] = s; s += fan * 256; idx++;
            fan = DH;
        }
        wp.src[idx] = final_w; wp.dstoff[idx] = wofff; wp.K[idx] = DCAT;
        wp.start[idx] = s; s += DCAT * 256;
        wp.start[10] = s;   // == WTOT
        wtsplit_all<<<cdiv(WTOT, 256), 256>>>(wp, Wth, Wtl);
    }

    // input split + zero counters/csum (one launch)
    copyx_both<<<cdiv((NS + NT) * 128, 256), 256>>>(x_s, NS, x_t, NT, Xh, Xl);
    fillinit_k<<<cdiv(5 * NMAX, 256), 256>>>(cnt_a, cnt_b, csum);

    // CSR build (both graphs, both directions)
    const int* s0 = edges, *d0 = edges + ES;
    const int* s1 = edget, *d1 = edget + ET;
    count_both<<<cdiv(ES + ET, 256), 256>>>(d0, s0, ES, d1, s1, ET, cnt_a, cnt_b);
    scan4_k<<<4, 1024>>>(cnt_a, cnt_b, off_a, off_b, cur_a, cur_b, inv_a, inv_b, ES);
    place_both<<<cdiv(ES + ET, 256), 256>>>(d0, s0, ES, d1, s1, ET,
                                            cur_a, cur_b, lst_a, lst_b);

    // GNN layers (both graphs batched, M = NTOT)
    int off = 0, fan = 128;
    for (int l = 0; l < 3; l++) {
        const __nv_bfloat16* Ahp = Xh + off;
        const __nv_bfloat16* Alp = Xl + off;
        dim3 g12(8, NTOT / 64);
        gemm_f<0><<<g12, 128>>>(Ahp, Alp, DCAT, Wth + woff12[l], Wtl + woff12[l],
                                tmp12, 512, NTOT, fan, nullptr, nullptr, nullptr,
                                nullptr, nullptr);
        gather2_k<<<2 * NTOT, 64>>>(tmp12, off_a, cnt_a, inv_a, lst_a, agg1,
                                    off_b, cnt_b, inv_b, lst_b, agg2);
        int noff = off + fan;
        dim3 gr(4, NTOT / 64);
        gemm_f<1><<<gr, 128>>>(Ahp, Alp, DCAT, Wth + woffr[l], Wtl + woffr[l],
                               nullptr, DCAT, NTOT, fan, br[l], agg1, agg2,
                               Xh + noff, Xl + noff);
        off = noff;
        fan = DH;
    }
    // final linear (K = 896)
    dim3 gridf(4, NTOT / 64);
    gemm_f<3><<<gridf, 128>>>(Xh, Xl, DCAT, Wth + wofff, Wtl + wofff,
                              Hf, DH, NTOT, DCAT, final_b, nullptr, nullptr,
                              nullptr, nullptr);
    l2split_k<<<NTOT, 256>>>(Hf, sh, sl, NS);

    // match GEMM (dummy rows: sh=0 -> exp(2e-9)==1.0f, matching reference pad)
    {
        dim3 gm(NMAX / 128, NMAX / 128);
        match_mma_kernel<<<gm, 256>>>(sh, sl, sh + (size_t)NMAX * DH,
                                      sl + (size_t)NMAX * DH, Eb);
    }

    // sinkhorn: colsum0, 4x fused (rowsum+colsum @ 256 CTAs), final rowsum, finalize
    colsum0_k<<<dim3(4, 128), 256>>>(Eb, csum);
    for (int it = 0; it < 4; it++)
        fused_rc<<<256, 256>>>(Eb, csum + it * NMAX, csum + (it + 1) * NMAX);
    recip_k<<<16, 256>>>(csum + 4 * NMAX, cinv, NMAX);
    rowsum_k<<<512, 256>>>(Eb, cinv, rr);
    finalize_k<<<cdiv(NS * (NMAX / 4), 256), 256>>>(Eb, rr, cinv,
                                                    (float*)d_out, NS);
}

// round 17
// speedup vs baseline: 1.5225x; 1.5225x over previous
#include <cuda_runtime.h>
#include <cuda_bf16.h>
#include <math.h>
#include <stdint.h>

#define NMAX 4096
#define NTOT 8192            // both graphs stacked
#define DH   256
#define DCAT 896
#define EMAX 65536
#define WTOT 720896

// ---------------- scratch (device globals; no runtime alloc) ----------------
__device__ __align__(16) __nv_bfloat16 g_Xh[(size_t)NTOT * DCAT];
__device__ __align__(16) __nv_bfloat16 g_Xl[(size_t)NTOT * DCAT];
__device__ __align__(16) __nv_bfloat16 g_Wth[WTOT];
__device__ __align__(16) __nv_bfloat16 g_Wtl[WTOT];
__device__ __align__(16) float g_tmp12[(size_t)NTOT * 512];
__device__ __align__(16) float g_agg1[(size_t)NTOT * DH];
__device__ __align__(16) float g_agg2[(size_t)NTOT * DH];
__device__ __align__(16) float g_H[(size_t)NTOT * DH];
__device__ __align__(16) float g_E[(size_t)NMAX * NMAX];   // 64MB (L2-resident)
__device__ __align__(16) float g_r[NMAX];
__device__ __align__(16) float g_csum[5 * NMAX];
__device__ __align__(16) float g_cinv[NMAX];
__device__ __align__(16) int   g_cnt_a[NTOT];
__device__ __align__(16) int   g_cnt_b[NTOT];
__device__ __align__(16) float g_inv_a[NTOT];
__device__ __align__(16) float g_inv_b[NTOT];
__device__ __align__(16) int g_off_a[NTOT];
__device__ __align__(16) int g_off_b[NTOT];
__device__ __align__(16) int g_cur_a[NTOT];
__device__ __align__(16) int g_cur_b[NTOT];
__device__ __align__(16) int g_lst_a[2 * EMAX];
__device__ __align__(16) int g_lst_b[2 * EMAX];
__device__ __align__(16) __nv_bfloat16 g_sh[(size_t)NTOT * DH];
__device__ __align__(16) __nv_bfloat16 g_sl[(size_t)NTOT * DH];

// ---------------- PTX helpers ----------------
__device__ __forceinline__ uint32_t smem_u32(const void* p) {
    uint32_t a;
    asm("{ .reg .u64 t; cvta.to.shared.u64 t, %1; cvt.u32.u64 %0, t; }" : "=r"(a) : "l"(p));
    return a;
}
#define CP_ASYNC16(saddr, gptr) \
    asm volatile("cp.async.cg.shared.global [%0], [%1], 16;" :: "r"(saddr), "l"(gptr))
#define CP_COMMIT() asm volatile("cp.async.commit_group;" ::: "memory")
#define CP_WAIT1()  asm volatile("cp.async.wait_group 1;" ::: "memory")

__device__ __forceinline__ void ldm_x4(uint32_t* r, uint32_t addr) {
    asm volatile("ldmatrix.sync.aligned.m8n8.x4.shared.b16 {%0,%1,%2,%3}, [%4];"
        : "=r"(r[0]), "=r"(r[1]), "=r"(r[2]), "=r"(r[3]) : "r"(addr));
}
__device__ __forceinline__ void mma_bf16(float* d, const uint32_t* a, uint32_t b0, uint32_t b1) {
    asm volatile(
        "mma.sync.aligned.m16n8k16.row.col.f32.bf16.bf16.f32 "
        "{%0,%1,%2,%3}, {%4,%5,%6,%7}, {%8,%9}, {%0,%1,%2,%3};"
        : "+f"(d[0]), "+f"(d[1]), "+f"(d[2]), "+f"(d[3])
        : "r"(a[0]), "r"(a[1]), "r"(a[2]), "r"(a[3]), "r"(b0), "r"(b1));
}

// ---------------- utility kernels ----------------
__global__ void fillinit_k(int* __restrict__ ca, int* __restrict__ cb,
                           float* __restrict__ cs)
{
    int t = blockIdx.x * blockDim.x + threadIdx.x;
    if (t < NTOT) { ca[t] = 0; cb[t] = 0; }
    if (t < 5 * NMAX) cs[t] = 0.f;
}
__global__ void recip_k(const float* __restrict__ a, float* __restrict__ b, int n) {
    int t = blockIdx.x * blockDim.x + threadIdx.x;
    if (t < n) b[t] = 1.0f / a[t];
}
__global__ void count_both(const int* __restrict__ d0, const int* __restrict__ s0, int E0,
                           const int* __restrict__ d1, const int* __restrict__ s1, int E1,
                           int* __restrict__ ca, int* __restrict__ cb)
{
    int t = blockIdx.x * blockDim.x + threadIdx.x;
    if (t < E0) {
        atomicAdd(&ca[d0[t]], 1); atomicAdd(&cb[s0[t]], 1);
    } else if (t < E0 + E1) {
        int u = t - E0;
        atomicAdd(&ca[NMAX + d1[u]], 1); atomicAdd(&cb[NMAX + s1[u]], 1);
    }
}
__global__ void scan4_k(const int* __restrict__ ca, const int* __restrict__ cb,
                        int* __restrict__ oa, int* __restrict__ ob,
                        int* __restrict__ ra, int* __restrict__ rb,
                        float* __restrict__ ia, float* __restrict__ ib, int E0)
{
    __shared__ int s[NMAX];
    int b = blockIdx.x;
    int gi = b & 1, dir = b >> 1;
    const int* cnt = (dir ? cb : ca) + gi * NMAX;
    int* off = (dir ? ob : oa) + gi * NMAX;
    int* cur = (dir ? rb : ra) + gi * NMAX;
    float* inv = (dir ? ib : ia) + gi * NMAX;
    int base = gi ? E0 : 0;
    int tid = threadIdx.x;
    #pragma unroll
    for (int j = 0; j < 4; j++) s[tid + j * 1024] = cnt[tid + j * 1024];
    __syncthreads();
    for (int d = 1; d < NMAX; d <<= 1) {
        int v[4];
        #pragma unroll
        for (int j = 0; j < 4; j++) {
            int i = tid + j * 1024;
            v[j] = (i >= d) ? s[i - d] : 0;
        }
        __syncthreads();
        #pragma unroll
        for (int j = 0; j < 4; j++) s[tid + j * 1024] += v[j];
        __syncthreads();
    }
    #pragma unroll
    for (int j = 0; j < 4; j++) {
        int i = tid + j * 1024;
        int c = cnt[i];
        int o = base + s[i] - c;
        off[i] = o;
        cur[i] = o;
        inv[i] = 1.0f / (float)max(c, 1);
    }
}
__global__ void place_both(const int* __restrict__ d0, const int* __restrict__ s0, int E0,
                           const int* __restrict__ d1, const int* __restrict__ s1, int E1,
                           int* __restrict__ ca, int* __restrict__ cb,
                           int* __restrict__ la, int* __restrict__ lb)
{
    int t = blockIdx.x * blockDim.x + threadIdx.x;
    if (t < E0) {
        int d = d0[t], s = s0[t];
        la[atomicAdd(&ca[d], 1)] = s;
        lb[atomicAdd(&cb[s], 1)] = d;
    } else if (t < E0 + E1) {
        int u = t - E0;
        int d = d1[u], s = s1[u];
        la[atomicAdd(&ca[NMAX + d], 1)] = NMAX + s;
        lb[atomicAdd(&cb[NMAX + s], 1)] = NMAX + d;
    }
}

// merged CSR gather-mean for BOTH directions: grid = 2*NTOT, 64 thr
__global__ void __launch_bounds__(64) gather2_k(
    const float* __restrict__ tmp12,
    const int* __restrict__ off_a, const int* __restrict__ cnt_a,
    const float* __restrict__ inv_a, const int* __restrict__ lst_a,
    float* __restrict__ agg1,
    const int* __restrict__ off_b, const int* __restrict__ cnt_b,
    const float* __restrict__ inv_b, const int* __restrict__ lst_b,
    float* __restrict__ agg2)
{
    __shared__ int sl[64];
    int n = blockIdx.x;
    const bool dirB = n >= NTOT;
    if (dirB) n -= NTOT;
    const float* vals = dirB ? tmp12 + 256 : tmp12;
    const int* off = dirB ? off_b : off_a;
    const int* cnt = dirB ? cnt_b : cnt_a;
    const float* inv = dirB ? inv_b : inv_a;
    const int* lst = dirB ? lst_b : lst_a;
    float* out = dirB ? agg2 : agg1;

    const int tid = threadIdx.x;
    const int beg = off[n];
    const int d = cnt[n];
    const int c4 = tid * 4;
    float4 acc = make_float4(0.f, 0.f, 0.f, 0.f);
    for (int base = 0; base < d; base += 64) {
        int chunk = min(64, d - base);
        if (tid < chunk) sl[tid] = lst[beg + base + tid];
        __syncthreads();
        int e = 0;
        for (; e + 4 <= chunk; e += 4) {
            float4 v0 = *reinterpret_cast<const float4*>(vals + (size_t)sl[e] * 512 + c4);
            float4 v1 = *reinterpret_cast<const float4*>(vals + (size_t)sl[e + 1] * 512 + c4);
            float4 v2 = *reinterpret_cast<const float4*>(vals + (size_t)sl[e + 2] * 512 + c4);
            float4 v3 = *reinterpret_cast<const float4*>(vals + (size_t)sl[e + 3] * 512 + c4);
            acc.x += (v0.x + v1.x) + (v2.x + v3.x);
            acc.y += (v0.y + v1.y) + (v2.y + v3.y);
            acc.z += (v0.z + v1.z) + (v2.z + v3.z);
            acc.w += (v0.w + v1.w) + (v2.w + v3.w);
        }
        for (; e < chunk; e++) {
            float4 v = *reinterpret_cast<const float4*>(vals + (size_t)sl[e] * 512 + c4);
            acc.x += v.x; acc.y += v.y; acc.z += v.z; acc.w += v.w;
        }
        __syncthreads();
    }
    float iv = inv[n];
    acc.x *= iv; acc.y *= iv; acc.z *= iv; acc.w *= iv;
    *reinterpret_cast<float4*>(out + (size_t)n * DH + c4) = acc;
}

// both graphs' input features -> bf16 hi/lo into X cols 0..127
__global__ void copyx_both(const float* __restrict__ xs, int NS,
                           const float* __restrict__ xt, int NT,
                           __nv_bfloat16* __restrict__ Xh, __nv_bfloat16* __restrict__ Xl)
{
    int t = blockIdx.x * blockDim.x + threadIdx.x;
    int n0 = NS * 128;
    float v;
    size_t dsti;
    if (t < n0) {
        v = xs[t];
        dsti = (size_t)(t >> 7) * DCAT + (t & 127);
    } else if (t < n0 + NT * 128) {
        int u = t - n0;
        v = xt[u];
        dsti = (size_t)(NMAX + (u >> 7)) * DCAT + (u & 127);
    } else return;
    __nv_bfloat16 h = __float2bfloat16(v);
    Xh[dsti] = h;
    Xl[dsti] = __float2bfloat16(v - __bfloat162float(h));
}

// all weights transpose+split in one kernel
struct WPack {
    const float* src[10];
    int dstoff[10];
    int K[10];
    int start[11];
};
__global__ void wtsplit_all(WPack wp, __nv_bfloat16* __restrict__ th,
                            __nv_bfloat16* __restrict__ tl)
{
    int t = blockIdx.x * blockDim.x + threadIdx.x;
    if (t >= WTOT) return;
    int seg = 0;
    #pragma unroll
    for (int i = 1; i < 10; i++) seg += (t >= wp.start[i]);
    int u = t - wp.start[seg];
    int K = wp.K[seg];
    int k = u >> 8, n = u & 255;          // src layout [K][256]
    float v = wp.src[seg][u];
    __nv_bfloat16 h = __float2bfloat16(v);
    size_t di = (size_t)wp.dstoff[seg] + (size_t)n * K + k;
    th[di] = h;
    tl[di] = __float2bfloat16(v - __bfloat162float(h));
}

// ---------------- fused GNN GEMM (single k-loop, cp.async 2-stage) ----------
#define GSP 40

template <int EPI>
__global__ void __launch_bounds__(128) gemm_f(
    const __nv_bfloat16* __restrict__ Ah, const __nv_bfloat16* __restrict__ Al, int lda,
    const __nv_bfloat16* __restrict__ Bh, const __nv_bfloat16* __restrict__ Bl,
    float* __restrict__ C, int ldc, int M, int K,
    const float* __restrict__ bias, const float* __restrict__ add1,
    const float* __restrict__ add2,
    __nv_bfloat16* __restrict__ Oh, __nv_bfloat16* __restrict__ Ol)
{
    __shared__ __nv_bfloat16 s[2][4][64 * GSP];
    const int tid = threadIdx.x;
    const int lane = tid & 31, wid = tid >> 5;
    const int wm = wid & 1, wn = wid >> 1;
    const int row0 = blockIdx.y * 64, col0 = blockIdx.x * 64;
    const int nk = K / 32;

    const __nv_bfloat16* base[4] = {
        Ah + (size_t)row0 * lda, Al + (size_t)row0 * lda,
        Bh + (size_t)col0 * K, Bl + (size_t)col0 * K };
    const int ld4[4] = { lda, lda, K, K };

    const int l_row = tid >> 1;
    const int l_q0 = (tid & 1) * 2;

    auto load_stage = [&](int kc, int st) {
        #pragma unroll
        for (int t4 = 0; t4 < 4; t4++) {
            const __nv_bfloat16* g = base[t4] + (size_t)l_row * ld4[t4] + kc * 32;
            uint32_t sa = smem_u32(&s[st][t4][l_row * GSP]);
            CP_ASYNC16(sa + (l_q0 + 0) * 16, g + (l_q0 + 0) * 8);
            CP_ASYNC16(sa + (l_q0 + 1) * 16, g + (l_q0 + 1) * 8);
        }
    };

    float acc[2][4][4];
    #pragma unroll
    for (int i = 0; i < 2; i++)
        #pragma unroll
        for (int j = 0; j < 4; j++)
            #pragma unroll
            for (int q = 0; q < 4; q++) acc[i][j][q] = 0.f;

    const int a_row = wm * 32 + (lane < 16 ? lane : lane - 16);
    const int a_col = (lane < 16 ? 0 : 8);
    const int b_row = wn * 32 + (lane & 7);
    const int b_col = (lane >> 3) * 8;

    load_stage(0, 0);
    CP_COMMIT();

    for (int kc = 0; kc < nk; kc++) {
        if (kc + 1 < nk) load_stage(kc + 1, (kc + 1) & 1);
        CP_COMMIT();
        CP_WAIT1();
        __syncthreads();
        const int st = kc & 1;

        uint32_t bh[4][4], bl[4][4];
        #pragma unroll
        for (int j = 0; j < 4; j++) {
            ldm_x4(bh[j], smem_u32(&s[st][2][(b_row + j * 8) * GSP + b_col]));
            ldm_x4(bl[j], smem_u32(&s[st][3][(b_row + j * 8) * GSP + b_col]));
        }
        #pragma unroll
        for (int h = 0; h < 2; h++) {
            #pragma unroll
            for (int i = 0; i < 2; i++) {
                uint32_t ah[4], al[4];
                ldm_x4(ah, smem_u32(&s[st][0][(a_row + i * 16) * GSP + h * 16 + a_col]));
                ldm_x4(al, smem_u32(&s[st][1][(a_row + i * 16) * GSP + h * 16 + a_col]));
                #pragma unroll
                for (int j = 0; j < 4; j++) {
                    mma_bf16(acc[i][j], ah, bh[j][2 * h], bh[j][2 * h + 1]);
                    mma_bf16(acc[i][j], ah, bl[j][2 * h], bl[j][2 * h + 1]);
                    mma_bf16(acc[i][j], al, bh[j][2 * h], bh[j][2 * h + 1]);
                }
            }
        }
        __syncthreads();
    }

    const int er = lane >> 2, ec = (lane & 3) * 2;
    #pragma unroll
    for (int i = 0; i < 2; i++) {
        #pragma unroll
        for (int j = 0; j < 4; j++) {
            int gc = col0 + wn * 32 + j * 8 + ec;
            #pragma unroll
            for (int rr = 0; rr < 2; rr++) {
                int row = row0 + wm * 32 + i * 16 + er + rr * 8;
                if (row >= M) continue;
                float v0 = acc[i][j][2 * rr + 0];
                float v1 = acc[i][j][2 * rr + 1];
                if (EPI == 0) {
                    *reinterpret_cast<float2*>(C + (size_t)row * ldc + gc) =
                        make_float2(v0, v1);
                } else if (EPI == 1) {
                    v0 = fmaxf(v0 + bias[gc] + add1[(size_t)row * DH + gc]
                                  + add2[(size_t)row * DH + gc], 0.f);
                    v1 = fmaxf(v1 + bias[gc + 1] + add1[(size_t)row * DH + gc + 1]
                                  + add2[(size_t)row * DH + gc + 1], 0.f);
                    __nv_bfloat16 h0 = __float2bfloat16(v0);
                    __nv_bfloat16 h1 = __float2bfloat16(v1);
                    __nv_bfloat16 l0 = __float2bfloat16(v0 - __bfloat162float(h0));
                    __nv_bfloat16 l1 = __float2bfloat16(v1 - __bfloat162float(h1));
                    __nv_bfloat162 hv; hv.x = h0; hv.y = h1;
                    __nv_bfloat162 lv; lv.x = l0; lv.y = l1;
                    *reinterpret_cast<__nv_bfloat162*>(Oh + (size_t)row * ldc + gc) = hv;
                    *reinterpret_cast<__nv_bfloat162*>(Ol + (size_t)row * ldc + gc) = lv;
                } else {  // EPI == 3
                    *reinterpret_cast<float2*>(C + (size_t)row * ldc + gc) =
                        make_float2(v0 + bias[gc], v1 + bias[gc + 1]);
                }
            }
        }
    }
}

// ---------------- match GEMM (3-pass, cp.async 2-stage) ----------------
#define SPAD 40

__global__ void __launch_bounds__(256, 2) match_mma_kernel(
    const __nv_bfloat16* __restrict__ Ah, const __nv_bfloat16* __restrict__ Al,
    const __nv_bfloat16* __restrict__ Bh, const __nv_bfloat16* __restrict__ Bl,
    float* __restrict__ Eout)
{
    __shared__ __nv_bfloat16 s[2][2][128 * SPAD];
    const int tid = threadIdx.x;
    const int wid = tid >> 5, lane = tid & 31;
    const int wm = wid & 3, wn = wid >> 2;
    const int row0 = blockIdx.y * 128, col0 = blockIdx.x * 128;

    const __nv_bfloat16* Asrc[3] = {
        Ah + (size_t)row0 * DH, Ah + (size_t)row0 * DH, Al + (size_t)row0 * DH };
    const __nv_bfloat16* Bsrc[3] = {
        Bh + (size_t)col0 * DH, Bl + (size_t)col0 * DH, Bh + (size_t)col0 * DH };

    const int l_row = tid >> 1;
    const int l_q0 = (tid & 1) * 2;

    auto load_stage = [&](int it, int st) {
        int p = it >> 3, kc = it & 7;
        const __nv_bfloat16* ga = Asrc[p] + (size_t)l_row * DH + kc * 32;
        const __nv_bfloat16* gb = Bsrc[p] + (size_t)l_row * DH + kc * 32;
        uint32_t sa = smem_u32(&s[st][0][l_row * SPAD]);
        uint32_t sb = smem_u32(&s[st][1][l_row * SPAD]);
        CP_ASYNC16(sa + (l_q0 + 0) * 16, ga + (l_q0 + 0) * 8);
        CP_ASYNC16(sa + (l_q0 + 1) * 16, ga + (l_q0 + 1) * 8);
        CP_ASYNC16(sb + (l_q0 + 0) * 16, gb + (l_q0 + 0) * 8);
        CP_ASYNC16(sb + (l_q0 + 1) * 16, gb + (l_q0 + 1) * 8);
    };

    float acc[2][8][4];
    #pragma unroll
    for (int i = 0; i < 2; i++)
        #pragma unroll
        for (int j = 0; j < 8; j++)
            #pragma unroll
            for (int q = 0; q < 4; q++) acc[i][j][q] = 0.f;

    const int a_row = wm * 32 + (lane < 16 ? lane : lane - 16);
    const int a_col = (lane < 16 ? 0 : 8);
    const int b_row = wn * 64 + (lane & 7);
    const int b_col = (lane >> 3) * 8;

    load_stage(0, 0);
    CP_COMMIT();

    for (int it = 0; it < 24; it++) {
        if (it + 1 < 24) load_stage(it + 1, (it + 1) & 1);
        CP_COMMIT();
        CP_WAIT1();
        __syncthreads();
        const int st = it & 1;

        uint32_t bfr[8][4];
        #pragma unroll
        for (int j = 0; j < 8; j++)
            ldm_x4(bfr[j], smem_u32(&s[st][1][(b_row + j * 8) * SPAD + b_col]));

        #pragma unroll
        for (int h = 0; h < 2; h++) {
            #pragma unroll
            for (int i = 0; i < 2; i++) {
                uint32_t afr[4];
                ldm_x4(afr, smem_u32(&s[st][0][(a_row + i * 16) * SPAD + h * 16 + a_col]));
                #pragma unroll
                for (int j = 0; j < 8; j++)
                    mma_bf16(acc[i][j], afr, bfr[j][2 * h], bfr[j][2 * h + 1]);
            }
        }
        __syncthreads();
    }

    const int er = lane >> 2, ec = (lane & 3) * 2;
    #pragma unroll
    for (int i = 0; i < 2; i++) {
        int gr0 = row0 + wm * 32 + i * 16 + er;
        #pragma unroll
        for (int j = 0; j < 8; j++) {
            int gc = col0 + wn * 64 + j * 8 + ec;
            float2 o0, o1;
            o0.x = __expf(20.f * (acc[i][j][0] + 1e-10f));
            o0.y = __expf(20.f * (acc[i][j][1] + 1e-10f));
            o1.x = __expf(20.f * (acc[i][j][2] + 1e-10f));
            o1.y = __expf(20.f * (acc[i][j][3] + 1e-10f));
            *reinterpret_cast<float2*>(Eout + (size_t)gr0 * NMAX + gc) = o0;
            *reinterpret_cast<float2*>(Eout + (size_t)(gr0 + 8) * NMAX + gc) = o1;
        }
    }
}

// ---------------- fused L2 normalize + bf16 split (zero dummy rows) --------
__global__ void l2split_k(const float* __restrict__ H, __nv_bfloat16* __restrict__ sh,
                          __nv_bfloat16* __restrict__ sl, int NS)
{
    int row = blockIdx.x;
    int tid = threadIdx.x;
    if (row >= NS && row < NMAX) {
        sh[(size_t)row * DH + tid] = __float2bfloat16(0.f);
        sl[(size_t)row * DH + tid] = __float2bfloat16(0.f);
        return;
    }
    float v = H[(size_t)row * DH + tid];
    __shared__ float red[256];
    red[tid] = v * v;
    __syncthreads();
    for (int s = 128; s > 0; s >>= 1) {
        if (tid < s) red[tid] += red[tid + s];
        __syncthreads();
    }
    float sc = 1.0f / fmaxf(sqrtf(red[0]), 1e-12f);
    float nv = v * sc;
    __nv_bfloat16 h = __float2bfloat16(nv);
    sh[(size_t)row * DH + tid] = h;
    sl[(size_t)row * DH + tid] = __float2bfloat16(nv - __bfloat162float(h));
}

// ---------------- sinkhorn factor passes ----------------
// colsum, float4 per thread: grid (4, 128) = 512 CTAs, 32 rows per CTA
template <bool HASR>
__global__ void colsum_k(const float* __restrict__ Eb, const float* __restrict__ r,
                         float* __restrict__ cs)
{
    int j4 = blockIdx.x * 256 + threadIdx.x;     // 0..1023
    int i0 = blockIdx.y * 32;
    const float4* E4 = reinterpret_cast<const float4*>(Eb);
    float4 acc = make_float4(0.f, 0.f, 0.f, 0.f);
    #pragma unroll 4
    for (int i = 0; i < 32; i++) {
        float4 e = E4[(size_t)(i0 + i) * (NMAX / 4) + j4];
        float ri = HASR ? __ldg(&r[i0 + i]) : 1.0f;
        acc.x += e.x * ri; acc.y += e.y * ri;
        acc.z += e.z * ri; acc.w += e.w * ri;
    }
    int c = j4 * 4;
    atomicAdd(&cs[c + 0], acc.x);
    atomicAdd(&cs[c + 1], acc.y);
    atomicAdd(&cs[c + 2], acc.z);
    atomicAdd(&cs[c + 3], acc.w);
}

// r[row] = 1/sum_j E[row][j]/csum[j]; warp-per-row, 8 rows/block, grid 512
// (reciprocal of csum computed inline during smem staging; MUFU hidden under LDG)
__global__ void __launch_bounds__(256) rowsum_k(const float* __restrict__ Eb,
                                                const float* __restrict__ csum,
                                                float* __restrict__ r)
{
    __shared__ float sc[NMAX];
    const int tid = threadIdx.x, lane = tid & 31, w = tid >> 5;
    #pragma unroll
    for (int j = 0; j < 4; j++) {
        float4 v = reinterpret_cast<const float4*>(csum)[tid + j * 256];
        float4 iv;
        iv.x = 1.0f / v.x; iv.y = 1.0f / v.y;
        iv.z = 1.0f / v.z; iv.w = 1.0f / v.w;
        reinterpret_cast<float4*>(sc)[tid + j * 256] = iv;
    }
    __syncthreads();
    const float4* sc4 = reinterpret_cast<const float4*>(sc);
    const int row = blockIdx.x * 8 + w;
    const float4* rp = reinterpret_cast<const float4*>(Eb + (size_t)row * NMAX);
    float acc = 0.f;
    #pragma unroll 8
    for (int k = 0; k < 32; k++) {
        float4 e = rp[lane + k * 32];
        float4 s4 = sc4[lane + k * 32];
        acc += e.x * s4.x + e.y * s4.y + e.z * s4.z + e.w * s4.w;
    }
    #pragma unroll
    for (int o = 16; o; o >>= 1) acc += __shfl_xor_sync(0xffffffffu, acc, o);
    if (lane == 0) r[row] = 1.0f / acc;
}

// out[i][j] = E[i][j]*r[i]*cinv[j]
__global__ void finalize_k(const float* __restrict__ Eb, const float* __restrict__ r,
                           const float* __restrict__ cinv, float* __restrict__ out, int rows)
{
    int t = blockIdx.x * blockDim.x + threadIdx.x;
    if (t >= rows * (NMAX / 4)) return;
    int i = t >> 10, j = t & 1023;
    float ri = r[i];
    float4 e = reinterpret_cast<const float4*>(Eb)[(size_t)i * (NMAX / 4) + j];
    float4 cv = reinterpret_cast<const float4*>(cinv)[j];
    float4 o;
    o.x = e.x * ri * cv.x; o.y = e.y * ri * cv.y;
    o.z = e.z * ri * cv.z; o.w = e.w * ri * cv.w;
    reinterpret_cast<float4*>(out)[t] = o;
}

// ---------------- host driver ----------------
static inline int cdiv(int a, int b) { return (a + b - 1) / b; }

extern "C" void kernel_launch(void* const* d_in, const int* in_sizes, int n_in,
                              void* d_out, int out_size)
{
    const float* x_s = (const float*)d_in[0];
    const float* x_t = (const float*)d_in[1];
    const int* edges = (const int*)d_in[2];
    const int* edget = (const int*)d_in[3];
    const float* W1[3], *W2[3], *Wr[3], *br[3];
    for (int l = 0; l < 3; l++) {
        W1[l] = (const float*)d_in[4 + 4 * l];
        W2[l] = (const float*)d_in[5 + 4 * l];
        Wr[l] = (const float*)d_in[6 + 4 * l];
        br[l] = (const float*)d_in[7 + 4 * l];
    }
    const float* final_w = (const float*)d_in[16];
    const float* final_b = (const float*)d_in[17];

    const int NS = in_sizes[0] / 128;
    const int NT = in_sizes[1] / 128;
    const int ES = in_sizes[2] / 2;
    const int ET = in_sizes[3] / 2;

    float *tmp12, *agg1, *agg2, *Hf, *Eb, *rr, *csum, *cinv, *inv_a, *inv_b;
    int *cnt_a, *cnt_b, *off_a, *off_b, *cur_a, *cur_b, *lst_a, *lst_b;
    __nv_bfloat16 *Xh, *Xl, *Wth, *Wtl, *sh, *sl;
    cudaGetSymbolAddress((void**)&Xh, g_Xh);
    cudaGetSymbolAddress((void**)&Xl, g_Xl);
    cudaGetSymbolAddress((void**)&Wth, g_Wth);
    cudaGetSymbolAddress((void**)&Wtl, g_Wtl);
    cudaGetSymbolAddress((void**)&tmp12, g_tmp12);
    cudaGetSymbolAddress((void**)&agg1, g_agg1);
    cudaGetSymbolAddress((void**)&agg2, g_agg2);
    cudaGetSymbolAddress((void**)&Hf, g_H);
    cudaGetSymbolAddress((void**)&Eb, g_E);
    cudaGetSymbolAddress((void**)&rr, g_r);
    cudaGetSymbolAddress((void**)&csum, g_csum);
    cudaGetSymbolAddress((void**)&cinv, g_cinv);
    cudaGetSymbolAddress((void**)&cnt_a, g_cnt_a);
    cudaGetSymbolAddress((void**)&cnt_b, g_cnt_b);
    cudaGetSymbolAddress((void**)&inv_a, g_inv_a);
    cudaGetSymbolAddress((void**)&inv_b, g_inv_b);
    cudaGetSymbolAddress((void**)&off_a, g_off_a);
    cudaGetSymbolAddress((void**)&off_b, g_off_b);
    cudaGetSymbolAddress((void**)&cur_a, g_cur_a);
    cudaGetSymbolAddress((void**)&cur_b, g_cur_b);
    cudaGetSymbolAddress((void**)&lst_a, g_lst_a);
    cudaGetSymbolAddress((void**)&lst_b, g_lst_b);
    cudaGetSymbolAddress((void**)&sh, g_sh);
    cudaGetSymbolAddress((void**)&sl, g_sl);

    // weight layout: per layer [W1;W2] fused [512][K], Wr [256][K], final [256][896]
    int woff12[3], woffr[3], wofff;
    {
        int o = 0, fan = 128;
        for (int l = 0; l < 3; l++) {
            woff12[l] = o; o += 512 * fan;
            woffr[l] = o;  o += 256 * fan;
            fan = DH;
        }
        wofff = o;
    }
    {
        WPack wp;
        int s = 0, fan = 128;
        int idx = 0;
        for (int l = 0; l < 3; l++) {
            wp.src[idx] = W1[l]; wp.dstoff[idx] = woff12[l];              wp.K[idx] = fan; wp.start[idx] = s; s += fan * 256; idx++;
            wp.src[idx] = W2[l]; wp.dstoff[idx] = woff12[l] + 256 * fan;  wp.K[idx] = fan; wp.start[idx] = s; s += fan * 256; idx++;
            wp.src[idx] = Wr[l]; wp.dstoff[idx] = woffr[l];               wp.K[idx] = fan; wp.start[idx] = s; s += fan * 256; idx++;
            fan = DH;
        }
        wp.src[idx] = final_w; wp.dstoff[idx] = wofff; wp.K[idx] = DCAT;
        wp.start[idx] = s; s += DCAT * 256;
        wp.start[10] = s;   // == WTOT
        wtsplit_all<<<cdiv(WTOT, 256), 256>>>(wp, Wth, Wtl);
    }

    // input split + zero counters/csum (one launch)
    copyx_both<<<cdiv((NS + NT) * 128, 256), 256>>>(x_s, NS, x_t, NT, Xh, Xl);
    fillinit_k<<<cdiv(5 * NMAX, 256), 256>>>(cnt_a, cnt_b, csum);

    // CSR build (both graphs, both directions)
    const int* s0 = edges, *d0 = edges + ES;
    const int* s1 = edget, *d1 = edget + ET;
    count_both<<<cdiv(ES + ET, 256), 256>>>(d0, s0, ES, d1, s1, ET, cnt_a, cnt_b);
    scan4_k<<<4, 1024>>>(cnt_a, cnt_b, off_a, off_b, cur_a, cur_b, inv_a, inv_b, ES);
    place_both<<<cdiv(ES + ET, 256), 256>>>(d0, s0, ES, d1, s1, ET,
                                            cur_a, cur_b, lst_a, lst_b);

    // GNN layers (both graphs batched, M = NTOT)
    int off = 0, fan = 128;
    for (int l = 0; l < 3; l++) {
        const __nv_bfloat16* Ahp = Xh + off;
        const __nv_bfloat16* Alp = Xl + off;
        dim3 g12(8, NTOT / 64);
        gemm_f<0><<<g12, 128>>>(Ahp, Alp, DCAT, Wth + woff12[l], Wtl + woff12[l],
                                tmp12, 512, NTOT, fan, nullptr, nullptr, nullptr,
                                nullptr, nullptr);
        gather2_k<<<2 * NTOT, 64>>>(tmp12, off_a, cnt_a, inv_a, lst_a, agg1,
                                    off_b, cnt_b, inv_b, lst_b, agg2);
        int noff = off + fan;
        dim3 gr(4, NTOT / 64);
        gemm_f<1><<<gr, 128>>>(Ahp, Alp, DCAT, Wth + woffr[l], Wtl + woffr[l],
                               nullptr, DCAT, NTOT, fan, br[l], agg1, agg2,
                               Xh + noff, Xl + noff);
        off = noff;
        fan = DH;
    }
    // final linear (K = 896)
    dim3 gridf(4, NTOT / 64);
    gemm_f<3><<<gridf, 128>>>(Xh, Xl, DCAT, Wth + wofff, Wtl + wofff,
                              Hf, DH, NTOT, DCAT, final_b, nullptr, nullptr,
                              nullptr, nullptr);
    l2split_k<<<NTOT, 256>>>(Hf, sh, sl, NS);

    // match GEMM (dummy rows: sh=0 -> exp(2e-9)==1.0f, matching reference pad)
    {
        dim3 gm(NMAX / 128, NMAX / 128);
        match_mma_kernel<<<gm, 256>>>(sh, sl, sh + (size_t)NMAX * DH,
                                      sl + (size_t)NMAX * DH, Eb);
    }

    // sinkhorn: 5x (col-norm, row-norm); rowsum inverts csum inline
    for (int it = 0; it < 5; it++) {
        float* cs = csum + it * NMAX;
        if (it == 0)
            colsum_k<false><<<dim3(4, 128), 256>>>(Eb, nullptr, cs);
        else
            colsum_k<true><<<dim3(4, 128), 256>>>(Eb, rr, cs);
        rowsum_k<<<512, 256>>>(Eb, cs, rr);
    }
    recip_k<<<16, 256>>>(csum + 4 * NMAX, cinv, NMAX);
    finalize_k<<<cdiv(NS * (NMAX / 4), 256), 256>>>(Eb, rr, cinv,
                                                    (float*)d_out, NS);
}